// round 4
// baseline (speedup 1.0000x reference)
#include <cuda_runtime.h>
#include <cstdint>

#define Bx    2
#define Lx    2048
#define Dx    1024
#define Hx    16
#define DHx   64
#define CKx   64
#define NCH   32          // Lx / CKx
#define ROWSx 4096        // Bx * Lx
#define BHx   32          // Bx * Hx

// Scratch (device globals: no allocation allowed in kernel_launch)
__device__ float g_qkv[ROWSx * 3 * Dx];           // [4096, 3072]
__device__ float g_y[ROWSx * Dx];                 // [4096, 1024] (tf32-rounded at producer)
__device__ float g_M[BHx * NCH * DHx * DHx];      // per-chunk state contribs
__device__ float g_P[BHx * NCH * DHx * DHx];      // exclusive prefix states
__device__ float g_xr[ROWSx * Dx];                // tf32-rounded x
__device__ float g_wq[3 * Dx * Dx];               // tf32-rounded Wqkv_w
__device__ float g_wo[Dx * Dx];                   // tf32-rounded out_w

// ============================================================================
// helpers (all non-"a" instructions: safe on plain sm_103 target)
// ============================================================================
__device__ __forceinline__ uint32_t smem_u32(const void* p) {
    uint32_t a;
    asm("{ .reg .u64 t; cvta.to.shared.u64 t, %1; cvt.u32.u64 %0, t; }"
        : "=r"(a) : "l"(p));
    return a;
}

__device__ __forceinline__ float rna_tf32(float x) {
    uint32_t u = __float_as_uint(x);
    asm("cvt.rna.tf32.f32 %0, %0;" : "+r"(u));
    return __uint_as_float(u);
}

#define CP16(dst, src) \
    asm volatile("cp.async.cg.shared.global [%0], [%1], 16;" :: "r"(dst), "l"(src) : "memory")
#define CP_COMMIT() asm volatile("cp.async.commit_group;" ::: "memory")
#define CP_WAIT2()  asm volatile("cp.async.wait_group 2;" ::: "memory")

#define LDSM4(r0, r1, r2, r3, addr) \
    asm volatile("ldmatrix.sync.aligned.m8n8.x4.shared.b16 {%0,%1,%2,%3}, [%4];" \
                 : "=r"(r0), "=r"(r1), "=r"(r2), "=r"(r3) : "r"(addr))

#define MMA_TF32(d, a, b) \
    asm volatile("mma.sync.aligned.m16n8k8.row.col.f32.tf32.tf32.f32 " \
                 "{%0,%1,%2,%3}, {%4,%5,%6,%7}, {%8,%9}, {%0,%1,%2,%3};" \
                 : "+f"((d)[0]), "+f"((d)[1]), "+f"((d)[2]), "+f"((d)[3]) \
                 : "r"((a)[0]), "r"((a)[1]), "r"((a)[2]), "r"((a)[3]), \
                   "r"((b)[0]), "r"((b)[1]))

// ============================================================================
// tf32 rounding pre-pass: dst[i] = rna_tf32(src[i]) (vectorized float4)
// ============================================================================
__global__ void __launch_bounds__(256) round_tf32_kernel(
    const float* __restrict__ src, float* __restrict__ dst, int n4)
{
    int i = blockIdx.x * 256 + threadIdx.x;
    if (i < n4) {
        float4 v = ((const float4*)src)[i];
        v.x = rna_tf32(v.x);
        v.y = rna_tf32(v.y);
        v.z = rna_tf32(v.z);
        v.w = rna_tf32(v.w);
        ((float4*)dst)[i] = v;
    }
}

// ============================================================================
// tf32 tensor-core GEMM (NT): C[M,N] = A[M,K] @ W[N,K]^T + bias[N]
// Inputs PRE-ROUNDED to tf32 values (no cvt in hot loop).
// CTA 128x128, BK=32, 256 thr (8 warps 4x2, warp tile 32x64), 4-stage cp.async
// ============================================================================
#define TBM 128
#define TBN 128
#define TBK 32
#define TSTG_BYTES (TBM * TBK * 4 + TBN * TBK * 4)   // 32768
#define TSMEM_TOTAL (4 * TSTG_BYTES)                 // 131072

__device__ __forceinline__ void tload(uint32_t stg, const float* __restrict__ A,
                                      const float* __restrict__ W, int K,
                                      int bm, int bn, int k0, int tid)
{
    #pragma unroll
    for (int j = 0; j < 4; j++) {
        int e = tid + j * 256;
        int r = e >> 3, c16 = e & 7;
        uint32_t dst = stg + (uint32_t)(r * 128 + ((c16 ^ (r & 7)) << 4));
        CP16(dst, A + (size_t)(bm + r) * K + k0 + c16 * 4);
    }
    #pragma unroll
    for (int j = 0; j < 4; j++) {
        int e = tid + j * 256;
        int r = e >> 3, c16 = e & 7;
        uint32_t dst = stg + 16384u + (uint32_t)(r * 128 + ((c16 ^ (r & 7)) << 4));
        CP16(dst, W + (size_t)(bn + r) * K + k0 + c16 * 4);
    }
}

__global__ void __launch_bounds__(256) gemm_tc_bias(
    const float* __restrict__ A, const float* __restrict__ W,
    const float* __restrict__ bias, float* __restrict__ C,
    int M, int N, int K)
{
    extern __shared__ char smem[];
    const uint32_t sb = smem_u32(smem);
    const int tid = threadIdx.x;
    const int lane = tid & 31, wid = tid >> 5;
    const int wm = wid & 3, wn = wid >> 2;
    const int bm = blockIdx.y * TBM;
    const int bn = blockIdx.x * TBN;
    const int NK = K / TBK;

    const int lrow = lane & 15;
    const int lkc  = lane >> 4;
    const int l7   = lrow & 7;

    uint32_t aRow[2], bRow[4];
    #pragma unroll
    for (int mt = 0; mt < 2; mt++) aRow[mt] = (uint32_t)((wm * 32 + mt * 16 + lrow) * 128);
    #pragma unroll
    for (int p = 0; p < 4; p++)    bRow[p] = (uint32_t)((wn * 64 + p * 16 + lrow) * 128);

    float d[2][8][4];
    #pragma unroll
    for (int mt = 0; mt < 2; mt++)
        #pragma unroll
        for (int nt = 0; nt < 8; nt++)
            #pragma unroll
            for (int i = 0; i < 4; i++) d[mt][nt][i] = 0.f;

    // Prologue: chunks 0..2 into stages 0..2
    #pragma unroll
    for (int i = 0; i < 3; i++) {
        tload(sb + (uint32_t)(i * TSTG_BYTES), A, W, K, bm, bn, i * TBK, tid);
        CP_COMMIT();
    }

    for (int i = 0; i < NK; i++) {
        const int stage = i & 3;
        CP_WAIT2();             // chunk i resident (pending: i+1, i+2)
        __syncthreads();
        if (i + 3 < NK)
            tload(sb + (uint32_t)(((i + 3) & 3) * TSTG_BYTES), A, W, K, bm, bn,
                  (i + 3) * TBK, tid);
        CP_COMMIT();            // uniform group count

        const uint32_t sA = sb + (uint32_t)(stage * TSTG_BYTES);
        const uint32_t sB = sA + 16384u;

        #pragma unroll
        for (int ks = 0; ks < 4; ks++) {
            const int kc = ks * 2;
            const uint32_t swz = (uint32_t)(((kc + lkc) ^ l7) << 4);

            uint32_t a[2][4];
            #pragma unroll
            for (int mt = 0; mt < 2; mt++)
                LDSM4(a[mt][0], a[mt][1], a[mt][2], a[mt][3], sA + aRow[mt] + swz);

            uint32_t b[8][2];
            #pragma unroll
            for (int p = 0; p < 4; p++) {
                uint32_t r0, r1, r2, r3;
                LDSM4(r0, r1, r2, r3, sB + bRow[p] + swz);
                b[2 * p][0] = r0; b[2 * p + 1][0] = r1;
                b[2 * p][1] = r2; b[2 * p + 1][1] = r3;
            }

            #pragma unroll
            for (int mt = 0; mt < 2; mt++)
                #pragma unroll
                for (int nt = 0; nt < 8; nt++)
                    MMA_TF32(d[mt][nt], a[mt], b[nt]);
        }
    }

    const int erow = lane >> 2;
    const int ecol = (lane & 3) * 2;
    #pragma unroll
    for (int mt = 0; mt < 2; mt++) {
        const int r0 = bm + wm * 32 + mt * 16 + erow;
        #pragma unroll
        for (int nt = 0; nt < 8; nt++) {
            const int c = bn + wn * 64 + nt * 8 + ecol;
            float2 bv = *(const float2*)(bias + c);
            float2 o0 = {d[mt][nt][0] + bv.x, d[mt][nt][1] + bv.y};
            float2 o1 = {d[mt][nt][2] + bv.x, d[mt][nt][3] + bv.y};
            *(float2*)(C + (size_t)r0 * N + c) = o0;
            *(float2*)(C + (size_t)(r0 + 8) * N + c) = o1;
        }
    }
}

// ---------------------------------------------------------------------------
// Attention kernel A: per (bh, chunk) of 64 tokens:
//   y_intra = tril(Q K^T) V        -> g_y
//   M       = V^T K (64x64 state)  -> g_M
// ---------------------------------------------------------------------------
__global__ void __launch_bounds__(256) attn_intra_kernel()
{
    __shared__ float sQt[64][64];
    __shared__ float sKt[64][64];
    __shared__ float sS[64][64];

    const int tid = threadIdx.x;
    const int tx = tid & 15, ty = tid >> 4;
    const int chunk = blockIdx.x, bh = blockIdx.y;
    const int b = bh >> 4, h = bh & 15;

    const float* qbase = g_qkv + ((size_t)(b * Lx + chunk * CKx)) * (3 * Dx) + h * DHx;
    const float* kbase = qbase + Dx;
    const float* vbase = qbase + 2 * Dx;
    const float sc = 0.125f;

    #pragma unroll
    for (int i = 0; i < 4; i++) {
        int e = tid + i * 256;
        int row = e >> 4, c4 = e & 15;
        float4 qv = *(const float4*)(qbase + (size_t)row * (3 * Dx) + c4 * 4);
        sQt[c4 * 4 + 0][row] = qv.x;
        sQt[c4 * 4 + 1][row] = qv.y;
        sQt[c4 * 4 + 2][row] = qv.z;
        sQt[c4 * 4 + 3][row] = qv.w;
        float4 kv = *(const float4*)(kbase + (size_t)row * (3 * Dx) + c4 * 4);
        sKt[c4 * 4 + 0][row] = kv.x * sc;
        sKt[c4 * 4 + 1][row] = kv.y * sc;
        sKt[c4 * 4 + 2][row] = kv.z * sc;
        sKt[c4 * 4 + 3][row] = kv.w * sc;
    }
    __syncthreads();

    float accS[4][4] = {};
    #pragma unroll 8
    for (int d = 0; d < 64; d++) {
        float4 a = *(const float4*)&sQt[d][ty * 4];
        float4 k4 = *(const float4*)&sKt[d][tx * 4];
        float ar[4] = {a.x, a.y, a.z, a.w};
        float kr[4] = {k4.x, k4.y, k4.z, k4.w};
        #pragma unroll
        for (int i = 0; i < 4; i++)
            #pragma unroll
            for (int j = 0; j < 4; j++)
                accS[i][j] += ar[i] * kr[j];
    }
    #pragma unroll
    for (int ii = 0; ii < 4; ii++) {
        int i = ty * 4 + ii;
        int j0 = tx * 4;
        float4 o;
        o.x = (i >= j0 + 0) ? accS[ii][0] : 0.f;
        o.y = (i >= j0 + 1) ? accS[ii][1] : 0.f;
        o.z = (i >= j0 + 2) ? accS[ii][2] : 0.f;
        o.w = (i >= j0 + 3) ? accS[ii][3] : 0.f;
        *(float4*)&sS[i][j0] = o;
    }
    __syncthreads();

    float (*sV)[64] = sQt;
    #pragma unroll
    for (int i = 0; i < 4; i++) {
        int e = tid + i * 256;
        int row = e >> 4, c4 = e & 15;
        *(float4*)&sV[row][c4 * 4] = *(const float4*)(vbase + (size_t)row * (3 * Dx) + c4 * 4);
    }
    __syncthreads();

    float accY[4][4] = {};
    #pragma unroll 8
    for (int j = 0; j < 64; j++) {
        float sa[4];
        #pragma unroll
        for (int ii = 0; ii < 4; ii++) sa[ii] = sS[ty * 4 + ii][j];
        float4 v4 = *(const float4*)&sV[j][tx * 4];
        float vr[4] = {v4.x, v4.y, v4.z, v4.w};
        #pragma unroll
        for (int ii = 0; ii < 4; ii++)
            #pragma unroll
            for (int cc = 0; cc < 4; cc++)
                accY[ii][cc] += sa[ii] * vr[cc];
    }

    float accM[4][4] = {};
    #pragma unroll 8
    for (int t = 0; t < 64; t++) {
        float4 v4 = *(const float4*)&sV[t][tx * 4];
        float va[4] = {v4.x, v4.y, v4.z, v4.w};
        float kb[4];
        #pragma unroll
        for (int jj = 0; jj < 4; jj++) kb[jj] = sKt[ty * 4 + jj][t];
        #pragma unroll
        for (int ii = 0; ii < 4; ii++)
            #pragma unroll
            for (int jj = 0; jj < 4; jj++)
                accM[ii][jj] += va[ii] * kb[jj];
    }

    float* ybase = g_y + ((size_t)(b * Lx + chunk * CKx)) * Dx + h * DHx;
    #pragma unroll
    for (int ii = 0; ii < 4; ii++) {
        int row = ty * 4 + ii;
        float4 o = {accY[ii][0], accY[ii][1], accY[ii][2], accY[ii][3]};
        *(float4*)(ybase + (size_t)row * Dx + tx * 4) = o;
    }

    __syncthreads();
    #pragma unroll
    for (int ii = 0; ii < 4; ii++)
        #pragma unroll
        for (int jj = 0; jj < 4; jj++)
            sS[tx * 4 + ii][ty * 4 + jj] = accM[ii][jj];
    __syncthreads();

    float* Mbase = g_M + ((size_t)(bh * NCH + chunk)) * (DHx * DHx);
    #pragma unroll
    for (int i = 0; i < 4; i++) {
        int e = tid + i * 256;
        int row = e >> 4, c4 = e & 15;
        *(float4*)(Mbase + row * 64 + c4 * 4) = *(const float4*)&sS[row][c4 * 4];
    }
}

// ---------------------------------------------------------------------------
// Exclusive prefix over chunks: P[c] = sum_{j<c} M[j]
// ---------------------------------------------------------------------------
__global__ void __launch_bounds__(256) prefix_kernel()
{
    const int bh = blockIdx.y;
    const int e = blockIdx.x * 256 + threadIdx.x;
    size_t base = (size_t)bh * NCH * (DHx * DHx) + e;
    float acc = 0.f;
    #pragma unroll 8
    for (int c = 0; c < NCH; c++) {
        g_P[base + (size_t)c * (DHx * DHx)] = acc;
        acc += g_M[base + (size_t)c * (DHx * DHx)];
    }
}

// ---------------------------------------------------------------------------
// Attention kernel C: y[t][c] += sum_b q[t][b] * P[c][b]; final y rounded to
// tf32 so the output GEMM needs no cvt.
// ---------------------------------------------------------------------------
__global__ void __launch_bounds__(256) attn_inter_kernel()
{
    __shared__ float sQt[64][64];
    __shared__ float sPt[64][64];

    const int tid = threadIdx.x;
    const int tx = tid & 15, ty = tid >> 4;
    const int chunk = blockIdx.x, bh = blockIdx.y;
    const int b = bh >> 4, h = bh & 15;

    const float* qbase = g_qkv + ((size_t)(b * Lx + chunk * CKx)) * (3 * Dx) + h * DHx;
    const float* Pbase = g_P + ((size_t)(bh * NCH + chunk)) * (DHx * DHx);

    #pragma unroll
    for (int i = 0; i < 4; i++) {
        int e = tid + i * 256;
        int row = e >> 4, c4 = e & 15;
        float4 qv = *(const float4*)(qbase + (size_t)row * (3 * Dx) + c4 * 4);
        sQt[c4 * 4 + 0][row] = qv.x;
        sQt[c4 * 4 + 1][row] = qv.y;
        sQt[c4 * 4 + 2][row] = qv.z;
        sQt[c4 * 4 + 3][row] = qv.w;
        float4 pv = *(const float4*)(Pbase + (size_t)row * 64 + c4 * 4);
        sPt[c4 * 4 + 0][row] = pv.x;
        sPt[c4 * 4 + 1][row] = pv.y;
        sPt[c4 * 4 + 2][row] = pv.z;
        sPt[c4 * 4 + 3][row] = pv.w;
    }
    __syncthreads();

    float acc[4][4] = {};
    #pragma unroll 8
    for (int bb = 0; bb < 64; bb++) {
        float4 a = *(const float4*)&sQt[bb][ty * 4];
        float4 p = *(const float4*)&sPt[bb][tx * 4];
        float ar[4] = {a.x, a.y, a.z, a.w};
        float pr[4] = {p.x, p.y, p.z, p.w};
        #pragma unroll
        for (int i = 0; i < 4; i++)
            #pragma unroll
            for (int j = 0; j < 4; j++)
                acc[i][j] += ar[i] * pr[j];
    }

    float* ybase = g_y + ((size_t)(b * Lx + chunk * CKx)) * Dx + h * DHx;
    #pragma unroll
    for (int ii = 0; ii < 4; ii++) {
        float4 old = *(const float4*)(ybase + (size_t)(ty * 4 + ii) * Dx + tx * 4);
        old.x = rna_tf32(old.x + acc[ii][0]);
        old.y = rna_tf32(old.y + acc[ii][1]);
        old.z = rna_tf32(old.z + acc[ii][2]);
        old.w = rna_tf32(old.w + acc[ii][3]);
        *(float4*)(ybase + (size_t)(ty * 4 + ii) * Dx + tx * 4) = old;
    }
}

// ---------------------------------------------------------------------------
extern "C" void kernel_launch(void* const* d_in, const int* in_sizes, int n_in,
                              void* d_out, int out_size)
{
    const float* x      = (const float*)d_in[0];   // [2,2048,1024]
    const float* Wqkv_w = (const float*)d_in[1];   // [3072,1024]
    const float* Wqkv_b = (const float*)d_in[2];   // [3072]
    const float* out_w  = (const float*)d_in[3];   // [1024,1024]
    const float* out_b  = (const float*)d_in[4];   // [1024]
    float* out = (float*)d_out;                    // [2,2048,1024]

    float *qkv_ptr, *y_ptr, *xr_ptr, *wq_ptr, *wo_ptr;
    cudaGetSymbolAddress((void**)&qkv_ptr, g_qkv);
    cudaGetSymbolAddress((void**)&y_ptr, g_y);
    cudaGetSymbolAddress((void**)&xr_ptr, g_xr);
    cudaGetSymbolAddress((void**)&wq_ptr, g_wq);
    cudaGetSymbolAddress((void**)&wo_ptr, g_wo);

    cudaFuncSetAttribute(gemm_tc_bias,
                         cudaFuncAttributeMaxDynamicSharedMemorySize, TSMEM_TOTAL);

    // 0. tf32-round inputs (once; removes all cvt from GEMM hot loops)
    round_tf32_kernel<<<(ROWSx * Dx / 4 + 255) / 256, 256>>>(x, xr_ptr, ROWSx * Dx / 4);
    round_tf32_kernel<<<(3 * Dx * Dx / 4 + 255) / 256, 256>>>(Wqkv_w, wq_ptr, 3 * Dx * Dx / 4);
    round_tf32_kernel<<<(Dx * Dx / 4 + 255) / 256, 256>>>(out_w, wo_ptr, Dx * Dx / 4);

    // 1. QKV projection: [4096,1024] @ [3072,1024]^T + b -> [4096,3072]
    gemm_tc_bias<<<dim3(3072 / TBN, ROWSx / TBM), 256, TSMEM_TOTAL>>>(
        xr_ptr, wq_ptr, Wqkv_b, qkv_ptr, ROWSx, 3 * Dx, Dx);

    // 2a. Intra-chunk attention + per-chunk states
    attn_intra_kernel<<<dim3(NCH, BHx), 256>>>();

    // 2b. Exclusive prefix of states
    prefix_kernel<<<dim3(16, BHx), 256>>>();

    // 2c. Inter-chunk contribution (rounds y to tf32 on store)
    attn_inter_kernel<<<dim3(NCH, BHx), 256>>>();

    // 3. Output projection: [4096,1024] @ [1024,1024]^T + b -> d_out
    gemm_tc_bias<<<dim3(Dx / TBN, ROWSx / TBM), 256, TSMEM_TOTAL>>>(
        y_ptr, wo_ptr, out_b, out, ROWSx, Dx, Dx);
}

// round 5
// speedup vs baseline: 1.5271x; 1.5271x over previous
#include <cuda_runtime.h>
#include <cuda_fp16.h>
#include <cstdint>

#define Bx    2
#define Lx    2048
#define Dx    1024
#define Hx    16
#define DHx   64
#define CKx   64
#define NCH   32          // Lx / CKx
#define ROWSx 4096        // Bx * Lx
#define BHx   32          // Bx * Hx

// Scratch (device globals: no allocation allowed in kernel_launch)
__device__ float  g_qkv[ROWSx * 3 * Dx];          // [4096, 3072] fp32
__device__ float  g_y[ROWSx * Dx];                // intra-chunk partial y (fp32)
__device__ float  g_M[BHx * NCH * DHx * DHx];     // per-chunk state contribs
__device__ float  g_P[BHx * NCH * DHx * DHx];     // exclusive prefix states
__device__ __half g_xh[ROWSx * Dx];               // fp16 x
__device__ __half g_wqh[3 * Dx * Dx];             // fp16 Wqkv_w
__device__ __half g_woh[Dx * Dx];                 // fp16 out_w
__device__ __half g_yh[ROWSx * Dx];               // fp16 final y (GEMM2 input)

// ============================================================================
// helpers (all non-"a" instructions: safe on plain sm_103 target)
// ============================================================================
__device__ __forceinline__ uint32_t smem_u32(const void* p) {
    uint32_t a;
    asm("{ .reg .u64 t; cvta.to.shared.u64 t, %1; cvt.u32.u64 %0, t; }"
        : "=r"(a) : "l"(p));
    return a;
}

#define CP16(dst, src) \
    asm volatile("cp.async.cg.shared.global [%0], [%1], 16;" :: "r"(dst), "l"(src) : "memory")
#define CP_COMMIT() asm volatile("cp.async.commit_group;" ::: "memory")
#define CP_WAIT1()  asm volatile("cp.async.wait_group 1;" ::: "memory")

#define LDSM4(r0, r1, r2, r3, addr) \
    asm volatile("ldmatrix.sync.aligned.m8n8.x4.shared.b16 {%0,%1,%2,%3}, [%4];" \
                 : "=r"(r0), "=r"(r1), "=r"(r2), "=r"(r3) : "r"(addr))

#define MMA_F16(d, a, b) \
    asm volatile("mma.sync.aligned.m16n8k16.row.col.f32.f16.f16.f32 " \
                 "{%0,%1,%2,%3}, {%4,%5,%6,%7}, {%8,%9}, {%0,%1,%2,%3};" \
                 : "+f"((d)[0]), "+f"((d)[1]), "+f"((d)[2]), "+f"((d)[3]) \
                 : "r"((a)[0]), "r"((a)[1]), "r"((a)[2]), "r"((a)[3]), \
                   "r"((b)[0]), "r"((b)[1]))

// ============================================================================
// fp32 -> fp16 conversion pre-pass (RN)
// ============================================================================
__global__ void __launch_bounds__(256) f2h_kernel(
    const float* __restrict__ src, __half* __restrict__ dst, int n4)
{
    int i = blockIdx.x * 256 + threadIdx.x;
    if (i < n4) {
        float4 v = ((const float4*)src)[i];
        ((__half2*)dst)[2 * i + 0] = __floats2half2_rn(v.x, v.y);
        ((__half2*)dst)[2 * i + 1] = __floats2half2_rn(v.z, v.w);
    }
}

// ============================================================================
// fp16 tensor-core GEMM (NT): C[M,N] = A[M,K] @ W[N,K]^T + bias[N]  (fp32 acc)
// CTA 128x128, BK=64 halves (128B rows), 256 thr (8 warps 4x2, warp 32x64),
// 3-stage cp.async, 96KB smem -> 2 CTAs/SM
// ============================================================================
#define TBM 128
#define TBN 128
#define HBK 64
#define TSTG_BYTES (TBM * 128 + TBN * 128)           // 32768
#define TSMEM_TOTAL (3 * TSTG_BYTES)                 // 98304

__device__ __forceinline__ void tload(uint32_t stg, const __half* __restrict__ A,
                                      const __half* __restrict__ W, int K,
                                      int bm, int bn, int k0, int tid)
{
    #pragma unroll
    for (int j = 0; j < 4; j++) {
        int e = tid + j * 256;
        int r = e >> 3, c16 = e & 7;
        uint32_t dst = stg + (uint32_t)(r * 128 + ((c16 ^ (r & 7)) << 4));
        CP16(dst, A + (size_t)(bm + r) * K + k0 + c16 * 8);
    }
    #pragma unroll
    for (int j = 0; j < 4; j++) {
        int e = tid + j * 256;
        int r = e >> 3, c16 = e & 7;
        uint32_t dst = stg + 16384u + (uint32_t)(r * 128 + ((c16 ^ (r & 7)) << 4));
        CP16(dst, W + (size_t)(bn + r) * K + k0 + c16 * 8);
    }
}

__global__ void __launch_bounds__(256, 2) gemm_tc_bias(
    const __half* __restrict__ A, const __half* __restrict__ W,
    const float* __restrict__ bias, float* __restrict__ C,
    int M, int N, int K)
{
    extern __shared__ char smem[];
    const uint32_t sb = smem_u32(smem);
    const int tid = threadIdx.x;
    const int lane = tid & 31, wid = tid >> 5;
    const int wm = wid & 3, wn = wid >> 2;
    const int bm = blockIdx.y * TBM;
    const int bn = blockIdx.x * TBN;
    const int NK = K / HBK;

    const int lrow = lane & 15;
    const int lkc  = lane >> 4;
    const int l7   = lrow & 7;

    uint32_t aRow[2], bRow[4];
    #pragma unroll
    for (int mt = 0; mt < 2; mt++) aRow[mt] = (uint32_t)((wm * 32 + mt * 16 + lrow) * 128);
    #pragma unroll
    for (int p = 0; p < 4; p++)    bRow[p] = (uint32_t)((wn * 64 + p * 16 + lrow) * 128);

    float d[2][8][4];
    #pragma unroll
    for (int mt = 0; mt < 2; mt++)
        #pragma unroll
        for (int nt = 0; nt < 8; nt++)
            #pragma unroll
            for (int i = 0; i < 4; i++) d[mt][nt][i] = 0.f;

    // Prologue: chunks 0,1 into stages 0,1
    tload(sb, A, W, K, bm, bn, 0, tid);
    CP_COMMIT();
    tload(sb + TSTG_BYTES, A, W, K, bm, bn, HBK, tid);
    CP_COMMIT();

    int s0 = 0, s2 = 2;     // stage of chunk i, stage for chunk i+2
    for (int i = 0; i < NK; i++) {
        CP_WAIT1();             // chunk i resident (pending: i+1)
        __syncthreads();
        if (i + 2 < NK)
            tload(sb + (uint32_t)(s2 * TSTG_BYTES), A, W, K, bm, bn, (i + 2) * HBK, tid);
        CP_COMMIT();            // uniform group count

        const uint32_t sA = sb + (uint32_t)(s0 * TSTG_BYTES);
        const uint32_t sB = sA + 16384u;

        #pragma unroll
        for (int ks = 0; ks < 4; ks++) {
            const int kc = ks * 2;                 // 16B-chunk base of this k16
            const uint32_t swz = (uint32_t)(((kc + lkc) ^ l7) << 4);

            uint32_t a[2][4];
            #pragma unroll
            for (int mt = 0; mt < 2; mt++)
                LDSM4(a[mt][0], a[mt][1], a[mt][2], a[mt][3], sA + aRow[mt] + swz);

            uint32_t b[8][2];
            #pragma unroll
            for (int p = 0; p < 4; p++) {
                uint32_t r0, r1, r2, r3;
                LDSM4(r0, r1, r2, r3, sB + bRow[p] + swz);
                b[2 * p][0] = r0; b[2 * p + 1][0] = r1;
                b[2 * p][1] = r2; b[2 * p + 1][1] = r3;
            }

            #pragma unroll
            for (int mt = 0; mt < 2; mt++)
                #pragma unroll
                for (int nt = 0; nt < 8; nt++)
                    MMA_F16(d[mt][nt], a[mt], b[nt]);
        }
        s0 = (s0 == 2) ? 0 : s0 + 1;
        s2 = (s2 == 2) ? 0 : s2 + 1;
    }

    const int erow = lane >> 2;
    const int ecol = (lane & 3) * 2;
    #pragma unroll
    for (int mt = 0; mt < 2; mt++) {
        const int r0 = bm + wm * 32 + mt * 16 + erow;
        #pragma unroll
        for (int nt = 0; nt < 8; nt++) {
            const int c = bn + wn * 64 + nt * 8 + ecol;
            float2 bv = *(const float2*)(bias + c);
            float2 o0 = {d[mt][nt][0] + bv.x, d[mt][nt][1] + bv.y};
            float2 o1 = {d[mt][nt][2] + bv.x, d[mt][nt][3] + bv.y};
            *(float2*)(C + (size_t)r0 * N + c) = o0;
            *(float2*)(C + (size_t)(r0 + 8) * N + c) = o1;
        }
    }
}

// ---------------------------------------------------------------------------
// Attention kernel A: per (bh, chunk) of 64 tokens:
//   y_intra = tril(Q K^T) V        -> g_y
//   M       = V^T K (64x64 state)  -> g_M
// ---------------------------------------------------------------------------
__global__ void __launch_bounds__(256) attn_intra_kernel()
{
    __shared__ float sQt[64][64];
    __shared__ float sKt[64][64];
    __shared__ float sS[64][64];

    const int tid = threadIdx.x;
    const int tx = tid & 15, ty = tid >> 4;
    const int chunk = blockIdx.x, bh = blockIdx.y;
    const int b = bh >> 4, h = bh & 15;

    const float* qbase = g_qkv + ((size_t)(b * Lx + chunk * CKx)) * (3 * Dx) + h * DHx;
    const float* kbase = qbase + Dx;
    const float* vbase = qbase + 2 * Dx;
    const float sc = 0.125f;

    #pragma unroll
    for (int i = 0; i < 4; i++) {
        int e = tid + i * 256;
        int row = e >> 4, c4 = e & 15;
        float4 qv = *(const float4*)(qbase + (size_t)row * (3 * Dx) + c4 * 4);
        sQt[c4 * 4 + 0][row] = qv.x;
        sQt[c4 * 4 + 1][row] = qv.y;
        sQt[c4 * 4 + 2][row] = qv.z;
        sQt[c4 * 4 + 3][row] = qv.w;
        float4 kv = *(const float4*)(kbase + (size_t)row * (3 * Dx) + c4 * 4);
        sKt[c4 * 4 + 0][row] = kv.x * sc;
        sKt[c4 * 4 + 1][row] = kv.y * sc;
        sKt[c4 * 4 + 2][row] = kv.z * sc;
        sKt[c4 * 4 + 3][row] = kv.w * sc;
    }
    __syncthreads();

    float accS[4][4] = {};
    #pragma unroll 8
    for (int d = 0; d < 64; d++) {
        float4 a = *(const float4*)&sQt[d][ty * 4];
        float4 k4 = *(const float4*)&sKt[d][tx * 4];
        float ar[4] = {a.x, a.y, a.z, a.w};
        float kr[4] = {k4.x, k4.y, k4.z, k4.w};
        #pragma unroll
        for (int i = 0; i < 4; i++)
            #pragma unroll
            for (int j = 0; j < 4; j++)
                accS[i][j] += ar[i] * kr[j];
    }
    #pragma unroll
    for (int ii = 0; ii < 4; ii++) {
        int i = ty * 4 + ii;
        int j0 = tx * 4;
        float4 o;
        o.x = (i >= j0 + 0) ? accS[ii][0] : 0.f;
        o.y = (i >= j0 + 1) ? accS[ii][1] : 0.f;
        o.z = (i >= j0 + 2) ? accS[ii][2] : 0.f;
        o.w = (i >= j0 + 3) ? accS[ii][3] : 0.f;
        *(float4*)&sS[i][j0] = o;
    }
    __syncthreads();

    float (*sV)[64] = sQt;
    #pragma unroll
    for (int i = 0; i < 4; i++) {
        int e = tid + i * 256;
        int row = e >> 4, c4 = e & 15;
        *(float4*)&sV[row][c4 * 4] = *(const float4*)(vbase + (size_t)row * (3 * Dx) + c4 * 4);
    }
    __syncthreads();

    float accY[4][4] = {};
    #pragma unroll 8
    for (int j = 0; j < 64; j++) {
        float sa[4];
        #pragma unroll
        for (int ii = 0; ii < 4; ii++) sa[ii] = sS[ty * 4 + ii][j];
        float4 v4 = *(const float4*)&sV[j][tx * 4];
        float vr[4] = {v4.x, v4.y, v4.z, v4.w};
        #pragma unroll
        for (int ii = 0; ii < 4; ii++)
            #pragma unroll
            for (int cc = 0; cc < 4; cc++)
                accY[ii][cc] += sa[ii] * vr[cc];
    }

    float accM[4][4] = {};
    #pragma unroll 8
    for (int t = 0; t < 64; t++) {
        float4 v4 = *(const float4*)&sV[t][tx * 4];
        float va[4] = {v4.x, v4.y, v4.z, v4.w};
        float kb[4];
        #pragma unroll
        for (int jj = 0; jj < 4; jj++) kb[jj] = sKt[ty * 4 + jj][t];
        #pragma unroll
        for (int ii = 0; ii < 4; ii++)
            #pragma unroll
            for (int jj = 0; jj < 4; jj++)
                accM[ii][jj] += va[ii] * kb[jj];
    }

    float* ybase = g_y + ((size_t)(b * Lx + chunk * CKx)) * Dx + h * DHx;
    #pragma unroll
    for (int ii = 0; ii < 4; ii++) {
        int row = ty * 4 + ii;
        float4 o = {accY[ii][0], accY[ii][1], accY[ii][2], accY[ii][3]};
        *(float4*)(ybase + (size_t)row * Dx + tx * 4) = o;
    }

    __syncthreads();
    #pragma unroll
    for (int ii = 0; ii < 4; ii++)
        #pragma unroll
        for (int jj = 0; jj < 4; jj++)
            sS[tx * 4 + ii][ty * 4 + jj] = accM[ii][jj];
    __syncthreads();

    float* Mbase = g_M + ((size_t)(bh * NCH + chunk)) * (DHx * DHx);
    #pragma unroll
    for (int i = 0; i < 4; i++) {
        int e = tid + i * 256;
        int row = e >> 4, c4 = e & 15;
        *(float4*)(Mbase + row * 64 + c4 * 4) = *(const float4*)&sS[row][c4 * 4];
    }
}

// ---------------------------------------------------------------------------
// Exclusive prefix over chunks: P[c] = sum_{j<c} M[j]
// ---------------------------------------------------------------------------
__global__ void __launch_bounds__(256) prefix_kernel()
{
    const int bh = blockIdx.y;
    const int e = blockIdx.x * 256 + threadIdx.x;
    size_t base = (size_t)bh * NCH * (DHx * DHx) + e;
    float acc = 0.f;
    #pragma unroll 8
    for (int c = 0; c < NCH; c++) {
        g_P[base + (size_t)c * (DHx * DHx)] = acc;
        acc += g_M[base + (size_t)c * (DHx * DHx)];
    }
}

// ---------------------------------------------------------------------------
// Attention kernel C: y_final[t][c] = y_intra + sum_b q[t][b] * P[c][b],
// written as fp16 directly into g_yh (GEMM2's A operand).
// ---------------------------------------------------------------------------
__global__ void __launch_bounds__(256) attn_inter_kernel()
{
    __shared__ float sQt[64][64];
    __shared__ float sPt[64][64];

    const int tid = threadIdx.x;
    const int tx = tid & 15, ty = tid >> 4;
    const int chunk = blockIdx.x, bh = blockIdx.y;
    const int b = bh >> 4, h = bh & 15;

    const float* qbase = g_qkv + ((size_t)(b * Lx + chunk * CKx)) * (3 * Dx) + h * DHx;
    const float* Pbase = g_P + ((size_t)(bh * NCH + chunk)) * (DHx * DHx);

    #pragma unroll
    for (int i = 0; i < 4; i++) {
        int e = tid + i * 256;
        int row = e >> 4, c4 = e & 15;
        float4 qv = *(const float4*)(qbase + (size_t)row * (3 * Dx) + c4 * 4);
        sQt[c4 * 4 + 0][row] = qv.x;
        sQt[c4 * 4 + 1][row] = qv.y;
        sQt[c4 * 4 + 2][row] = qv.z;
        sQt[c4 * 4 + 3][row] = qv.w;
        float4 pv = *(const float4*)(Pbase + (size_t)row * 64 + c4 * 4);
        sPt[c4 * 4 + 0][row] = pv.x;
        sPt[c4 * 4 + 1][row] = pv.y;
        sPt[c4 * 4 + 2][row] = pv.z;
        sPt[c4 * 4 + 3][row] = pv.w;
    }
    __syncthreads();

    float acc[4][4] = {};
    #pragma unroll 8
    for (int bb = 0; bb < 64; bb++) {
        float4 a = *(const float4*)&sQt[bb][ty * 4];
        float4 p = *(const float4*)&sPt[bb][tx * 4];
        float ar[4] = {a.x, a.y, a.z, a.w};
        float pr[4] = {p.x, p.y, p.z, p.w};
        #pragma unroll
        for (int i = 0; i < 4; i++)
            #pragma unroll
            for (int j = 0; j < 4; j++)
                acc[i][j] += ar[i] * pr[j];
    }

    const float* ybase = g_y + ((size_t)(b * Lx + chunk * CKx)) * Dx + h * DHx;
    __half* yhbase = g_yh + ((size_t)(b * Lx + chunk * CKx)) * Dx + h * DHx;
    #pragma unroll
    for (int ii = 0; ii < 4; ii++) {
        float4 old = *(const float4*)(ybase + (size_t)(ty * 4 + ii) * Dx + tx * 4);
        float2 lo = {old.x + acc[ii][0], old.y + acc[ii][1]};
        float2 hi = {old.z + acc[ii][2], old.w + acc[ii][3]};
        __half2* dst = (__half2*)(yhbase + (size_t)(ty * 4 + ii) * Dx + tx * 4);
        dst[0] = __floats2half2_rn(lo.x, lo.y);
        dst[1] = __floats2half2_rn(hi.x, hi.y);
    }
}

// ---------------------------------------------------------------------------
extern "C" void kernel_launch(void* const* d_in, const int* in_sizes, int n_in,
                              void* d_out, int out_size)
{
    const float* x      = (const float*)d_in[0];   // [2,2048,1024]
    const float* Wqkv_w = (const float*)d_in[1];   // [3072,1024]
    const float* Wqkv_b = (const float*)d_in[2];   // [3072]
    const float* out_w  = (const float*)d_in[3];   // [1024,1024]
    const float* out_b  = (const float*)d_in[4];   // [1024]
    float* out = (float*)d_out;                    // [2,2048,1024]

    float *qkv_ptr;
    __half *xh_ptr, *wq_ptr, *wo_ptr, *yh_ptr;
    cudaGetSymbolAddress((void**)&qkv_ptr, g_qkv);
    cudaGetSymbolAddress((void**)&xh_ptr, g_xh);
    cudaGetSymbolAddress((void**)&wq_ptr, g_wqh);
    cudaGetSymbolAddress((void**)&wo_ptr, g_woh);
    cudaGetSymbolAddress((void**)&yh_ptr, g_yh);

    cudaFuncSetAttribute(gemm_tc_bias,
                         cudaFuncAttributeMaxDynamicSharedMemorySize, TSMEM_TOTAL);

    // 0. fp16 conversion of GEMM operands
    f2h_kernel<<<(ROWSx * Dx / 4 + 255) / 256, 256>>>(x, xh_ptr, ROWSx * Dx / 4);
    f2h_kernel<<<(3 * Dx * Dx / 4 + 255) / 256, 256>>>(Wqkv_w, wq_ptr, 3 * Dx * Dx / 4);
    f2h_kernel<<<(Dx * Dx / 4 + 255) / 256, 256>>>(out_w, wo_ptr, Dx * Dx / 4);

    // 1. QKV projection: [4096,1024] @ [3072,1024]^T + b -> [4096,3072] fp32
    gemm_tc_bias<<<dim3(3072 / TBN, ROWSx / TBM), 256, TSMEM_TOTAL>>>(
        xh_ptr, wq_ptr, Wqkv_b, qkv_ptr, ROWSx, 3 * Dx, Dx);

    // 2a. Intra-chunk attention + per-chunk states
    attn_intra_kernel<<<dim3(NCH, BHx), 256>>>();

    // 2b. Exclusive prefix of states
    prefix_kernel<<<dim3(16, BHx), 256>>>();

    // 2c. Inter-chunk contribution -> fp16 y
    attn_inter_kernel<<<dim3(NCH, BHx), 256>>>();

    // 3. Output projection: [4096,1024] @ [1024,1024]^T + b -> d_out
    gemm_tc_bias<<<dim3(Dx / TBN, ROWSx / TBM), 256, TSMEM_TOTAL>>>(
        yh_ptr, wo_ptr, out_b, out, ROWSx, Dx, Dx);
}

// round 6
// speedup vs baseline: 2.1978x; 1.4392x over previous
#include <cuda_runtime.h>
#include <cuda_fp16.h>
#include <cstdint>

#define Bx    2
#define Lx    2048
#define Dx    1024
#define Hx    16
#define DHx   64
#define CKx   64
#define NCH   32          // Lx / CKx
#define ROWSx 4096        // Bx * Lx
#define BHx   32          // Bx * Hx

// Scratch (device globals: no allocation allowed in kernel_launch)
__device__ __align__(16) __half g_qkvh[ROWSx * 3 * Dx];  // fp16 qkv (GEMM1 out)
__device__ float  g_y[ROWSx * Dx];                       // intra-chunk partial y (fp32)
__device__ float  g_M[BHx * NCH * DHx * DHx];            // per-chunk states (fp32)
__device__ __align__(16) __half g_Ph[BHx * NCH * DHx * DHx]; // exclusive prefix (fp16)
__device__ __align__(16) __half g_xh[ROWSx * Dx];        // fp16 x
__device__ __align__(16) __half g_wqh[3 * Dx * Dx];      // fp16 Wqkv_w
__device__ __align__(16) __half g_woh[Dx * Dx];          // fp16 out_w
__device__ __align__(16) __half g_yh[ROWSx * Dx];        // fp16 final y (GEMM2 in)

// ============================================================================
// helpers (all non-"a" instructions: safe on plain sm_103 target)
// ============================================================================
__device__ __forceinline__ uint32_t smem_u32(const void* p) {
    uint32_t a;
    asm("{ .reg .u64 t; cvta.to.shared.u64 t, %1; cvt.u32.u64 %0, t; }"
        : "=r"(a) : "l"(p));
    return a;
}

#define CP16(dst, src) \
    asm volatile("cp.async.cg.shared.global [%0], [%1], 16;" :: "r"(dst), "l"(src) : "memory")
#define CP_COMMIT() asm volatile("cp.async.commit_group;" ::: "memory")
#define CP_WAIT0()  asm volatile("cp.async.wait_group 0;" ::: "memory")
#define CP_WAIT1()  asm volatile("cp.async.wait_group 1;" ::: "memory")

#define LDSM4(r0, r1, r2, r3, addr) \
    asm volatile("ldmatrix.sync.aligned.m8n8.x4.shared.b16 {%0,%1,%2,%3}, [%4];" \
                 : "=r"(r0), "=r"(r1), "=r"(r2), "=r"(r3) : "r"(addr))

#define LDSM4T(r0, r1, r2, r3, addr) \
    asm volatile("ldmatrix.sync.aligned.m8n8.x4.trans.shared.b16 {%0,%1,%2,%3}, [%4];" \
                 : "=r"(r0), "=r"(r1), "=r"(r2), "=r"(r3) : "r"(addr))

#define MMA_F16(d, a, b) \
    asm volatile("mma.sync.aligned.m16n8k16.row.col.f32.f16.f16.f32 " \
                 "{%0,%1,%2,%3}, {%4,%5,%6,%7}, {%8,%9}, {%0,%1,%2,%3};" \
                 : "+f"((d)[0]), "+f"((d)[1]), "+f"((d)[2]), "+f"((d)[3]) \
                 : "r"((a)[0]), "r"((a)[1]), "r"((a)[2]), "r"((a)[3]), \
                   "r"((b)[0]), "r"((b)[1]))

__device__ __forceinline__ void st2(float* p, float x, float y) {
    *(float2*)p = make_float2(x, y);
}
__device__ __forceinline__ void st2(__half* p, float x, float y) {
    *(__half2*)p = __floats2half2_rn(x, y);
}

// ============================================================================
// fp32 -> fp16 conversion pre-pass (RN)
// ============================================================================
__global__ void __launch_bounds__(256) f2h_kernel(
    const float* __restrict__ src, __half* __restrict__ dst, int n4)
{
    int i = blockIdx.x * 256 + threadIdx.x;
    if (i < n4) {
        float4 v = ((const float4*)src)[i];
        ((__half2*)dst)[2 * i + 0] = __floats2half2_rn(v.x, v.y);
        ((__half2*)dst)[2 * i + 1] = __floats2half2_rn(v.z, v.w);
    }
}

// ============================================================================
// fp16 tensor-core GEMM (NT): C[M,N] = A[M,K] @ W[N,K]^T + bias[N]  (fp32 acc)
// CTA 128x128, BK=64 halves (128B rows), 256 thr (8 warps 4x2, warp 32x64),
// 3-stage cp.async, 96KB smem -> 2 CTAs/SM. Output type templated (fp16/fp32).
// ============================================================================
#define TBM 128
#define TBN 128
#define HBK 64
#define TSTG_BYTES (TBM * 128 + TBN * 128)           // 32768
#define TSMEM_TOTAL (3 * TSTG_BYTES)                 // 98304

__device__ __forceinline__ void tload(uint32_t stg, const __half* __restrict__ A,
                                      const __half* __restrict__ W, int K,
                                      int bm, int bn, int k0, int tid)
{
    #pragma unroll
    for (int j = 0; j < 4; j++) {
        int e = tid + j * 256;
        int r = e >> 3, c16 = e & 7;
        uint32_t dst = stg + (uint32_t)(r * 128 + ((c16 ^ (r & 7)) << 4));
        CP16(dst, A + (size_t)(bm + r) * K + k0 + c16 * 8);
    }
    #pragma unroll
    for (int j = 0; j < 4; j++) {
        int e = tid + j * 256;
        int r = e >> 3, c16 = e & 7;
        uint32_t dst = stg + 16384u + (uint32_t)(r * 128 + ((c16 ^ (r & 7)) << 4));
        CP16(dst, W + (size_t)(bn + r) * K + k0 + c16 * 8);
    }
}

template <typename OT>
__global__ void __launch_bounds__(256, 2) gemm_tc_bias(
    const __half* __restrict__ A, const __half* __restrict__ W,
    const float* __restrict__ bias, OT* __restrict__ C,
    int M, int N, int K)
{
    extern __shared__ char smem[];
    const uint32_t sb = smem_u32(smem);
    const int tid = threadIdx.x;
    const int lane = tid & 31, wid = tid >> 5;
    const int wm = wid & 3, wn = wid >> 2;
    const int bm = blockIdx.y * TBM;
    const int bn = blockIdx.x * TBN;
    const int NK = K / HBK;

    const int lrow = lane & 15;
    const int lkc  = lane >> 4;
    const int l7   = lrow & 7;

    uint32_t aRow[2], bRow[4];
    #pragma unroll
    for (int mt = 0; mt < 2; mt++) aRow[mt] = (uint32_t)((wm * 32 + mt * 16 + lrow) * 128);
    #pragma unroll
    for (int p = 0; p < 4; p++)    bRow[p] = (uint32_t)((wn * 64 + p * 16 + lrow) * 128);

    float d[2][8][4];
    #pragma unroll
    for (int mt = 0; mt < 2; mt++)
        #pragma unroll
        for (int nt = 0; nt < 8; nt++)
            #pragma unroll
            for (int i = 0; i < 4; i++) d[mt][nt][i] = 0.f;

    tload(sb, A, W, K, bm, bn, 0, tid);
    CP_COMMIT();
    tload(sb + TSTG_BYTES, A, W, K, bm, bn, HBK, tid);
    CP_COMMIT();

    int s0 = 0, s2 = 2;
    for (int i = 0; i < NK; i++) {
        CP_WAIT1();
        __syncthreads();
        if (i + 2 < NK)
            tload(sb + (uint32_t)(s2 * TSTG_BYTES), A, W, K, bm, bn, (i + 2) * HBK, tid);
        CP_COMMIT();

        const uint32_t sA = sb + (uint32_t)(s0 * TSTG_BYTES);
        const uint32_t sB = sA + 16384u;

        #pragma unroll
        for (int ks = 0; ks < 4; ks++) {
            const int kc = ks * 2;
            const uint32_t swz = (uint32_t)(((kc + lkc) ^ l7) << 4);

            uint32_t a[2][4];
            #pragma unroll
            for (int mt = 0; mt < 2; mt++)
                LDSM4(a[mt][0], a[mt][1], a[mt][2], a[mt][3], sA + aRow[mt] + swz);

            uint32_t b[8][2];
            #pragma unroll
            for (int p = 0; p < 4; p++) {
                uint32_t r0, r1, r2, r3;
                LDSM4(r0, r1, r2, r3, sB + bRow[p] + swz);
                b[2 * p][0] = r0; b[2 * p + 1][0] = r1;
                b[2 * p][1] = r2; b[2 * p + 1][1] = r3;
            }

            #pragma unroll
            for (int mt = 0; mt < 2; mt++)
                #pragma unroll
                for (int nt = 0; nt < 8; nt++)
                    MMA_F16(d[mt][nt], a[mt], b[nt]);
        }
        s0 = (s0 == 2) ? 0 : s0 + 1;
        s2 = (s2 == 2) ? 0 : s2 + 1;
    }

    const int erow = lane >> 2;
    const int ecol = (lane & 3) * 2;
    #pragma unroll
    for (int mt = 0; mt < 2; mt++) {
        const int r0 = bm + wm * 32 + mt * 16 + erow;
        #pragma unroll
        for (int nt = 0; nt < 8; nt++) {
            const int c = bn + wn * 64 + nt * 8 + ecol;
            float2 bv = *(const float2*)(bias + c);
            st2(C + (size_t)r0 * N + c, d[mt][nt][0] + bv.x, d[mt][nt][1] + bv.y);
            st2(C + (size_t)(r0 + 8) * N + c, d[mt][nt][2] + bv.x, d[mt][nt][3] + bv.y);
        }
    }
}

// ============================================================================
// Attention kernel A (fp16 MMA): per (bh, chunk) of 64 tokens:
//   S = tril(Q K^T) * 0.125 ;  Y = S V -> g_y (fp32) ;  M = V^T K * 0.125 -> g_M
// 128 threads (4 warps), warp tile 16x64.
// ============================================================================
__global__ void __launch_bounds__(128) attn_intra_kernel()
{
    __shared__ __half sQ[64 * 64], sK[64 * 64], sV[64 * 64], sS[64 * 64];

    const int tid = threadIdx.x, lane = tid & 31, w = tid >> 5;
    const int chunk = blockIdx.x, bh = blockIdx.y;
    const int b = bh >> 4, h = bh & 15;

    const uint32_t q_s = smem_u32(sQ), k_s = smem_u32(sK);
    const uint32_t v_s = smem_u32(sV), s_s = smem_u32(sS);

    const __half* base = g_qkvh + (size_t)(b * Lx + chunk * CKx) * (3 * Dx) + h * DHx;
    #pragma unroll
    for (int j = 0; j < 4; j++) {
        int e = tid + j * 128;
        int r = e >> 3, c16 = e & 7;
        uint32_t off = (uint32_t)(r * 128 + ((c16 ^ (r & 7)) << 4));
        const __half* src = base + (size_t)r * (3 * Dx) + c16 * 8;
        CP16(q_s + off, src);
        CP16(k_s + off, src + Dx);
        CP16(v_s + off, src + 2 * Dx);
    }
    CP_COMMIT();
    CP_WAIT0();
    __syncthreads();

    const int lrow = lane & 15, lkc = lane >> 4, l7 = lrow & 7;
    const int erow = lane >> 2, ecol = (lane & 3) * 2;
    const uint32_t aRowOff = (uint32_t)((w * 16 + lrow) * 128);

    // ---- Phase 1: S = Q K^T (NT) ----
    float accS[8][4];
    #pragma unroll
    for (int nt = 0; nt < 8; nt++)
        #pragma unroll
        for (int i = 0; i < 4; i++) accS[nt][i] = 0.f;

    #pragma unroll
    for (int ks = 0; ks < 4; ks++) {
        const uint32_t swz = (uint32_t)(((ks * 2 + lkc) ^ l7) << 4);
        uint32_t a[4];
        LDSM4(a[0], a[1], a[2], a[3], q_s + aRowOff + swz);
        uint32_t bf[8][2];
        #pragma unroll
        for (int p = 0; p < 4; p++) {
            uint32_t r0, r1, r2, r3;
            LDSM4(r0, r1, r2, r3, k_s + (uint32_t)((p * 16 + lrow) * 128) + swz);
            bf[2 * p][0] = r0; bf[2 * p + 1][0] = r1;
            bf[2 * p][1] = r2; bf[2 * p + 1][1] = r3;
        }
        #pragma unroll
        for (int nt = 0; nt < 8; nt++) MMA_F16(accS[nt], a, bf[nt]);
    }

    // scale + causal mask + fp16 -> sS (swizzled)
    #pragma unroll
    for (int nt = 0; nt < 8; nt++) {
        const int i0 = w * 16 + erow, i1 = i0 + 8;
        const int j0 = nt * 8 + ecol;
        float s00 = (i0 >= j0)     ? accS[nt][0] * 0.125f : 0.f;
        float s01 = (i0 >= j0 + 1) ? accS[nt][1] * 0.125f : 0.f;
        float s10 = (i1 >= j0)     ? accS[nt][2] * 0.125f : 0.f;
        float s11 = (i1 >= j0 + 1) ? accS[nt][3] * 0.125f : 0.f;
        const uint32_t cb = (uint32_t)(j0 * 2);
        uint32_t o0 = (uint32_t)(i0 * 128) + (((cb >> 4) ^ (uint32_t)(i0 & 7)) << 4) + (cb & 15);
        uint32_t o1 = (uint32_t)(i1 * 128) + (((cb >> 4) ^ (uint32_t)(i1 & 7)) << 4) + (cb & 15);
        *(__half2*)((char*)sS + o0) = __floats2half2_rn(s00, s01);
        *(__half2*)((char*)sS + o1) = __floats2half2_rn(s10, s11);
    }
    __syncthreads();

    // ---- Phase 2: Y = S V (NN: B via ldmatrix.trans) ----
    float accY[8][4];
    #pragma unroll
    for (int nt = 0; nt < 8; nt++)
        #pragma unroll
        for (int i = 0; i < 4; i++) accY[nt][i] = 0.f;

    #pragma unroll
    for (int ks = 0; ks < 4; ks++) {
        const int kbase = ks * 16;
        const uint32_t swz = (uint32_t)(((ks * 2 + lkc) ^ l7) << 4);
        uint32_t a[4];
        LDSM4(a[0], a[1], a[2], a[3], s_s + aRowOff + swz);
        uint32_t bf[8][2];
        #pragma unroll
        for (int nb = 0; nb < 4; nb++) {
            const int vr = kbase + lrow;
            const uint32_t c16 = (uint32_t)(nb * 2 + lkc);
            uint32_t r0, r1, r2, r3;
            LDSM4T(r0, r1, r2, r3, v_s + (uint32_t)(vr * 128) + ((c16 ^ (uint32_t)(vr & 7)) << 4));
            bf[2 * nb][0] = r0; bf[2 * nb][1] = r1;
            bf[2 * nb + 1][0] = r2; bf[2 * nb + 1][1] = r3;
        }
        #pragma unroll
        for (int nt = 0; nt < 8; nt++) MMA_F16(accY[nt], a, bf[nt]);
    }

    float* yb = g_y + (size_t)(b * Lx + chunk * CKx) * Dx + h * DHx;
    #pragma unroll
    for (int nt = 0; nt < 8; nt++) {
        const int i0 = w * 16 + erow, j0 = nt * 8 + ecol;
        st2(yb + (size_t)i0 * Dx + j0, accY[nt][0], accY[nt][1]);
        st2(yb + (size_t)(i0 + 8) * Dx + j0, accY[nt][2], accY[nt][3]);
    }

    // ---- Phase 3: M = V^T K * 0.125 (A via trans, B via trans) ----
    float accM[8][4];
    #pragma unroll
    for (int nt = 0; nt < 8; nt++)
        #pragma unroll
        for (int i = 0; i < 4; i++) accM[nt][i] = 0.f;

    const int abase = w * 16;
    const int arow_lo = (lane & 7) + ((lane >> 4) << 3);
    const uint32_t ac16 = (uint32_t)((abase >> 3) + ((lane >> 3) & 1));

    #pragma unroll
    for (int ks = 0; ks < 4; ks++) {
        const int kbase = ks * 16;
        const int vr = kbase + arow_lo;
        uint32_t a[4];
        LDSM4T(a[0], a[1], a[2], a[3],
               v_s + (uint32_t)(vr * 128) + ((ac16 ^ (uint32_t)(vr & 7)) << 4));
        uint32_t bf[8][2];
        #pragma unroll
        for (int nb = 0; nb < 4; nb++) {
            const int kr = kbase + lrow;
            const uint32_t c16 = (uint32_t)(nb * 2 + lkc);
            uint32_t r0, r1, r2, r3;
            LDSM4T(r0, r1, r2, r3, k_s + (uint32_t)(kr * 128) + ((c16 ^ (uint32_t)(kr & 7)) << 4));
            bf[2 * nb][0] = r0; bf[2 * nb][1] = r1;
            bf[2 * nb + 1][0] = r2; bf[2 * nb + 1][1] = r3;
        }
        #pragma unroll
        for (int nt = 0; nt < 8; nt++) MMA_F16(accM[nt], a, bf[nt]);
    }

    float* Mb = g_M + (size_t)(bh * NCH + chunk) * (DHx * DHx);
    #pragma unroll
    for (int nt = 0; nt < 8; nt++) {
        const int a0 = w * 16 + erow, j0 = nt * 8 + ecol;
        st2(Mb + a0 * 64 + j0, accM[nt][0] * 0.125f, accM[nt][1] * 0.125f);
        st2(Mb + (a0 + 8) * 64 + j0, accM[nt][2] * 0.125f, accM[nt][3] * 0.125f);
    }
}

// ---------------------------------------------------------------------------
// Exclusive prefix over chunks (fp32 accumulate, fp16 out): P[c] = sum_{j<c} M[j]
// ---------------------------------------------------------------------------
__global__ void __launch_bounds__(256) prefix_kernel()
{
    const int bh = blockIdx.y;
    const int e = blockIdx.x * 256 + threadIdx.x;
    size_t base = (size_t)bh * NCH * (DHx * DHx) + e;
    float acc = 0.f;
    #pragma unroll 8
    for (int c = 0; c < NCH; c++) {
        g_Ph[base + (size_t)c * (DHx * DHx)] = __float2half_rn(acc);
        acc += g_M[base + (size_t)c * (DHx * DHx)];
    }
}

// ============================================================================
// Attention kernel C (fp16 MMA): y_final[t][c] = y_intra + sum_b q[t][b] P[c][b]
// -> g_yh fp16.  128 threads (4 warps), warp tile 16x64.
// ============================================================================
__global__ void __launch_bounds__(128) attn_inter_kernel()
{
    __shared__ __half sQ[64 * 64], sP[64 * 64];

    const int tid = threadIdx.x, lane = tid & 31, w = tid >> 5;
    const int chunk = blockIdx.x, bh = blockIdx.y;
    const int b = bh >> 4, h = bh & 15;

    const uint32_t q_s = smem_u32(sQ), p_s = smem_u32(sP);

    const __half* qbase = g_qkvh + (size_t)(b * Lx + chunk * CKx) * (3 * Dx) + h * DHx;
    const __half* Pbase = g_Ph + (size_t)(bh * NCH + chunk) * (DHx * DHx);
    #pragma unroll
    for (int j = 0; j < 4; j++) {
        int e = tid + j * 128;
        int r = e >> 3, c16 = e & 7;
        uint32_t off = (uint32_t)(r * 128 + ((c16 ^ (r & 7)) << 4));
        CP16(q_s + off, qbase + (size_t)r * (3 * Dx) + c16 * 8);
        CP16(p_s + off, Pbase + r * 64 + c16 * 8);
    }
    CP_COMMIT();
    CP_WAIT0();
    __syncthreads();

    const int lrow = lane & 15, lkc = lane >> 4, l7 = lrow & 7;
    const int erow = lane >> 2, ecol = (lane & 3) * 2;
    const uint32_t aRowOff = (uint32_t)((w * 16 + lrow) * 128);

    // y_inter = Q P^T (NT: both row-major over k-dim b)
    float acc[8][4];
    #pragma unroll
    for (int nt = 0; nt < 8; nt++)
        #pragma unroll
        for (int i = 0; i < 4; i++) acc[nt][i] = 0.f;

    #pragma unroll
    for (int ks = 0; ks < 4; ks++) {
        const uint32_t swz = (uint32_t)(((ks * 2 + lkc) ^ l7) << 4);
        uint32_t a[4];
        LDSM4(a[0], a[1], a[2], a[3], q_s + aRowOff + swz);
        uint32_t bf[8][2];
        #pragma unroll
        for (int p = 0; p < 4; p++) {
            uint32_t r0, r1, r2, r3;
            LDSM4(r0, r1, r2, r3, p_s + (uint32_t)((p * 16 + lrow) * 128) + swz);
            bf[2 * p][0] = r0; bf[2 * p + 1][0] = r1;
            bf[2 * p][1] = r2; bf[2 * p + 1][1] = r3;
        }
        #pragma unroll
        for (int nt = 0; nt < 8; nt++) MMA_F16(acc[nt], a, bf[nt]);
    }

    const float* yb = g_y + (size_t)(b * Lx + chunk * CKx) * Dx + h * DHx;
    __half* yh = g_yh + (size_t)(b * Lx + chunk * CKx) * Dx + h * DHx;
    #pragma unroll
    for (int nt = 0; nt < 8; nt++) {
        const int i0 = w * 16 + erow, j0 = nt * 8 + ecol;
        float2 v0 = *(const float2*)(yb + (size_t)i0 * Dx + j0);
        float2 v1 = *(const float2*)(yb + (size_t)(i0 + 8) * Dx + j0);
        *(__half2*)(yh + (size_t)i0 * Dx + j0) =
            __floats2half2_rn(v0.x + acc[nt][0], v0.y + acc[nt][1]);
        *(__half2*)(yh + (size_t)(i0 + 8) * Dx + j0) =
            __floats2half2_rn(v1.x + acc[nt][2], v1.y + acc[nt][3]);
    }
}

// ---------------------------------------------------------------------------
extern "C" void kernel_launch(void* const* d_in, const int* in_sizes, int n_in,
                              void* d_out, int out_size)
{
    const float* x      = (const float*)d_in[0];   // [2,2048,1024]
    const float* Wqkv_w = (const float*)d_in[1];   // [3072,1024]
    const float* Wqkv_b = (const float*)d_in[2];   // [3072]
    const float* out_w  = (const float*)d_in[3];   // [1024,1024]
    const float* out_b  = (const float*)d_in[4];   // [1024]
    float* out = (float*)d_out;                    // [2,2048,1024]

    __half *qkvh_ptr, *xh_ptr, *wq_ptr, *wo_ptr, *yh_ptr;
    cudaGetSymbolAddress((void**)&qkvh_ptr, g_qkvh);
    cudaGetSymbolAddress((void**)&xh_ptr, g_xh);
    cudaGetSymbolAddress((void**)&wq_ptr, g_wqh);
    cudaGetSymbolAddress((void**)&wo_ptr, g_woh);
    cudaGetSymbolAddress((void**)&yh_ptr, g_yh);

    cudaFuncSetAttribute(gemm_tc_bias<__half>,
                         cudaFuncAttributeMaxDynamicSharedMemorySize, TSMEM_TOTAL);
    cudaFuncSetAttribute(gemm_tc_bias<float>,
                         cudaFuncAttributeMaxDynamicSharedMemorySize, TSMEM_TOTAL);

    // 0. fp16 conversion of GEMM operands
    f2h_kernel<<<(ROWSx * Dx / 4 + 255) / 256, 256>>>(x, xh_ptr, ROWSx * Dx / 4);
    f2h_kernel<<<(3 * Dx * Dx / 4 + 255) / 256, 256>>>(Wqkv_w, wq_ptr, 3 * Dx * Dx / 4);
    f2h_kernel<<<(Dx * Dx / 4 + 255) / 256, 256>>>(out_w, wo_ptr, Dx * Dx / 4);

    // 1. QKV projection -> fp16 qkv
    gemm_tc_bias<__half><<<dim3(3072 / TBN, ROWSx / TBM), 256, TSMEM_TOTAL>>>(
        xh_ptr, wq_ptr, Wqkv_b, qkvh_ptr, ROWSx, 3 * Dx, Dx);

    // 2a. Intra-chunk attention + per-chunk states (tensor cores)
    attn_intra_kernel<<<dim3(NCH, BHx), 128>>>();

    // 2b. Exclusive prefix of states (fp32 acc -> fp16 P)
    prefix_kernel<<<dim3(16, BHx), 256>>>();

    // 2c. Inter-chunk contribution (tensor cores) -> fp16 y
    attn_inter_kernel<<<dim3(NCH, BHx), 128>>>();

    // 3. Output projection -> fp32 out
    gemm_tc_bias<float><<<dim3(Dx / TBN, ROWSx / TBM), 256, TSMEM_TOTAL>>>(
        yh_ptr, wo_ptr, out_b, out, ROWSx, Dx, Dx);
}